// round 1
// baseline (speedup 1.0000x reference)
#include <cuda_runtime.h>

#define NPTS 96
#define HDIM 64
#define RANK 32

// Scratch for the per-axis factor matrices: f[axis][r][n], n contiguous.
__device__ float g_f[4 * RANK * NPTS];

// ---------------------------------------------------------------------------
// Kernel 1: evaluate the four tiny MLPs.
// grid = 4 (one block per axis), block = 96 threads (one per collocation pt).
// ---------------------------------------------------------------------------
__global__ void mlp_kernel(const float* __restrict__ t, const float* __restrict__ x,
                           const float* __restrict__ y, const float* __restrict__ z,
                           const float* __restrict__ W1, const float* __restrict__ b1,
                           const float* __restrict__ W2, const float* __restrict__ b2,
                           const float* __restrict__ W3, const float* __restrict__ b3) {
    const int axis = blockIdx.x;
    const int n = threadIdx.x;

    __shared__ float sW2[HDIM * HDIM];   // 16 KB
    __shared__ float sW3[HDIM * RANK];   // 8 KB

    for (int idx = n; idx < HDIM * HDIM; idx += blockDim.x)
        sW2[idx] = W2[axis * HDIM * HDIM + idx];
    for (int idx = n; idx < HDIM * RANK; idx += blockDim.x)
        sW3[idx] = W3[axis * HDIM * RANK + idx];
    __syncthreads();

    const float* coord = (axis == 0) ? t : (axis == 1) ? x : (axis == 2) ? y : z;
    const float c = coord[n];

    float h1[HDIM];
#pragma unroll
    for (int j = 0; j < HDIM; j++)
        h1[j] = tanhf(c * W1[axis * HDIM + j] + b1[axis * HDIM + j]);

    float h2[HDIM];
#pragma unroll
    for (int k = 0; k < HDIM; k++) {
        float acc = b2[axis * HDIM + k];
#pragma unroll
        for (int j = 0; j < HDIM; j++)
            acc += h1[j] * sW2[j * HDIM + k];
        h2[k] = tanhf(acc);
    }

#pragma unroll
    for (int r = 0; r < RANK; r++) {
        float acc = b3[axis * RANK + r];
#pragma unroll
        for (int k = 0; k < HDIM; k++)
            acc += h2[k] * sW3[k * RANK + r];
        g_f[axis * RANK * NPTS + r * NPTS + n] = acc;
    }
}

// ---------------------------------------------------------------------------
// Kernel 2: rank-32 CP reconstruction using packed f32x2 FMA (FFMA2).
// One block per (t,x) pair; each block produces the full 96x96 (y,z) tile.
// ---------------------------------------------------------------------------
__device__ __forceinline__ unsigned long long ffma2(unsigned long long a,
                                                    unsigned long long b,
                                                    unsigned long long c) {
    unsigned long long d;
    asm("fma.rn.f32x2 %0, %1, %2, %3;" : "=l"(d) : "l"(a), "l"(b), "l"(c));
    return d;
}

__global__ void __launch_bounds__(256) cp_kernel(float* __restrict__ out) {
    __shared__ float sw[RANK];
    __shared__ unsigned long long sA[NPTS * RANK];  // a[y][r] duplicated as (v,v): 24 KB
    __shared__ float sFz[RANK * NPTS];              // fz[r][z], z contiguous: 12 KB

    const float* ft = g_f + 0 * RANK * NPTS;
    const float* fx = g_f + 1 * RANK * NPTS;
    const float* fy = g_f + 2 * RANK * NPTS;
    const float* fz = g_f + 3 * RANK * NPTS;

    const int bid = blockIdx.x;
    const int tc = bid / NPTS;   // t index
    const int xc = bid % NPTS;   // x index
    const int tid = threadIdx.x;

    // w[r] = ft[r,t] * fx[r,x]
    if (tid < RANK) sw[tid] = ft[tid * NPTS + tc] * fx[tid * NPTS + xc];
    __syncthreads();

    // a[y][r] = fy[r,y] * w[r], duplicated into both f32x2 lanes
    for (int idx = tid; idx < NPTS * RANK; idx += 256) {
        int yy = idx >> 5;
        int r  = idx & 31;
        float v = fy[r * NPTS + yy] * sw[r];
        ((float2*)sA)[idx] = make_float2(v, v);
    }
    // fz tile into shared (64-bit loadable z-pairs)
    for (int idx = tid; idx < RANK * NPTS; idx += 256) sFz[idx] = fz[idx];
    __syncthreads();

    const int tz = tid & 15;   // 16 z-groups of 6 (= 3 pairs)
    const int ty = tid >> 4;   // 16 y-groups of 6
    const int ybase = ty * 6;
    const int zbase = tz * 6;  // even -> 8B aligned pairs

    unsigned long long acc[6][3];
#pragma unroll
    for (int a = 0; a < 6; a++)
#pragma unroll
        for (int b = 0; b < 3; b++) acc[a][b] = 0ULL;

#pragma unroll 4
    for (int r = 0; r < RANK; r++) {
        const unsigned long long fz0 =
            *(const unsigned long long*)(sFz + r * NPTS + zbase);
        const unsigned long long fz1 =
            *(const unsigned long long*)(sFz + r * NPTS + zbase + 2);
        const unsigned long long fz2 =
            *(const unsigned long long*)(sFz + r * NPTS + zbase + 4);
#pragma unroll
        for (int yy = 0; yy < 6; yy++) {
            const unsigned long long av = sA[(ybase + yy) * RANK + r];
            acc[yy][0] = ffma2(av, fz0, acc[yy][0]);
            acc[yy][1] = ffma2(av, fz1, acc[yy][1]);
            acc[yy][2] = ffma2(av, fz2, acc[yy][2]);
        }
    }

    // Store 6x6 tile: addresses are 8B aligned (zbase even).
    unsigned long long* out64 = (unsigned long long*)out;
    const size_t base = (size_t)bid * (NPTS * NPTS);
#pragma unroll
    for (int yy = 0; yy < 6; yy++) {
        const size_t off = base + (size_t)(ybase + yy) * NPTS + zbase;
        out64[(off >> 1) + 0] = acc[yy][0];
        out64[(off >> 1) + 1] = acc[yy][1];
        out64[(off >> 1) + 2] = acc[yy][2];
    }
}

// ---------------------------------------------------------------------------
extern "C" void kernel_launch(void* const* d_in, const int* in_sizes, int n_in,
                              void* d_out, int out_size) {
    const float* t  = (const float*)d_in[0];
    const float* x  = (const float*)d_in[1];
    const float* y  = (const float*)d_in[2];
    const float* z  = (const float*)d_in[3];
    const float* W1 = (const float*)d_in[4];
    const float* b1 = (const float*)d_in[5];
    const float* W2 = (const float*)d_in[6];
    const float* b2 = (const float*)d_in[7];
    const float* W3 = (const float*)d_in[8];
    const float* b3 = (const float*)d_in[9];
    float* out = (float*)d_out;

    mlp_kernel<<<4, NPTS>>>(t, x, y, z, W1, b1, W2, b2, W3, b3);
    cp_kernel<<<NPTS * NPTS, 256>>>(out);
}

// round 2
// speedup vs baseline: 1.8898x; 1.8898x over previous
#include <cuda_runtime.h>

#define NPTS 96
#define HDIM 64
#define RANK 32
#define MTOT (NPTS * NPTS)   // 9216
#define BM 128
#define BN 256

// Factor matrices per axis: f[axis][r][n], n contiguous.
__device__ float g_f[4 * RANK * NPTS];
// GEMM operands, r-major: A[r][(t,x)], B[r][(y,z)].
__device__ float g_A[RANK * MTOT];
__device__ float g_B[RANK * MTOT];

// ---------------------------------------------------------------------------
// Kernel 1: four tiny MLPs. grid=4 (axis), block=384 = (96 points x 4 quarters)
// ---------------------------------------------------------------------------
__global__ void __launch_bounds__(384) mlp_kernel(
    const float* __restrict__ t, const float* __restrict__ x,
    const float* __restrict__ y, const float* __restrict__ z,
    const float* __restrict__ W1, const float* __restrict__ b1,
    const float* __restrict__ W2, const float* __restrict__ b2,
    const float* __restrict__ W3, const float* __restrict__ b3) {
    const int axis = blockIdx.x;
    const int tid = threadIdx.x;
    const int n = tid % NPTS;
    const int q = tid / NPTS;          // 0..3

    __shared__ float sW2[HDIM * HDIM];      // 16 KB (reused for W3 in stage C)
    __shared__ float sh2[HDIM * NPTS];      // [k][n], 24 KB

    for (int idx = tid; idx < HDIM * HDIM; idx += 384)
        sW2[idx] = W2[axis * HDIM * HDIM + idx];
    __syncthreads();

    const float* coord = (axis == 0) ? t : (axis == 1) ? x : (axis == 2) ? y : z;
    const float c = coord[n];

    // h1 (computed redundantly in each quarter — cheap)
    float h1[HDIM];
#pragma unroll
    for (int j = 0; j < HDIM; j++)
        h1[j] = tanhf(fmaf(c, __ldg(&W1[axis * HDIM + j]), __ldg(&b1[axis * HDIM + j])));

    // h2: this thread owns k in [q*16, q*16+16)
#pragma unroll
    for (int kk = 0; kk < 16; kk++) {
        const int k = q * 16 + kk;
        float a0 = 0.f, a1 = 0.f, a2 = 0.f, a3 = 0.f;
#pragma unroll
        for (int j = 0; j < HDIM; j += 4) {
            a0 = fmaf(h1[j + 0], sW2[(j + 0) * HDIM + k], a0);
            a1 = fmaf(h1[j + 1], sW2[(j + 1) * HDIM + k], a1);
            a2 = fmaf(h1[j + 2], sW2[(j + 2) * HDIM + k], a2);
            a3 = fmaf(h1[j + 3], sW2[(j + 3) * HDIM + k], a3);
        }
        sh2[k * NPTS + n] = tanhf((a0 + a1) + (a2 + a3) + __ldg(&b2[axis * HDIM + k]));
    }
    __syncthreads();

    // reuse sW2 buffer for W3 [HDIM][RANK]
    for (int idx = tid; idx < HDIM * RANK; idx += 384)
        sW2[idx] = W3[axis * HDIM * RANK + idx];
    __syncthreads();

    // output: this thread owns r in [q*8, q*8+8)
#pragma unroll
    for (int rr = 0; rr < 8; rr++) {
        const int r = q * 8 + rr;
        float a0 = 0.f, a1 = 0.f, a2 = 0.f, a3 = 0.f;
#pragma unroll
        for (int k = 0; k < HDIM; k += 4) {
            a0 = fmaf(sh2[(k + 0) * NPTS + n], sW2[(k + 0) * RANK + r], a0);
            a1 = fmaf(sh2[(k + 1) * NPTS + n], sW2[(k + 1) * RANK + r], a1);
            a2 = fmaf(sh2[(k + 2) * NPTS + n], sW2[(k + 2) * RANK + r], a2);
            a3 = fmaf(sh2[(k + 3) * NPTS + n], sW2[(k + 3) * RANK + r], a3);
        }
        g_f[axis * RANK * NPTS + r * NPTS + n] =
            (a0 + a1) + (a2 + a3) + __ldg(&b3[axis * RANK + r]);
    }
}

// ---------------------------------------------------------------------------
// Kernel 2: build GEMM operands. A[r][t*96+x] = ft[r][t]*fx[r][x]; B likewise.
// ---------------------------------------------------------------------------
__global__ void __launch_bounds__(256) prep_kernel() {
    const int idx = blockIdx.x * 256 + threadIdx.x;   // grid exact: RANK*MTOT
    const int r = idx / MTOT;
    const int p = idx - r * MTOT;
    const int i = p / NPTS;
    const int j = p - i * NPTS;
    const float* ft = g_f + 0 * RANK * NPTS;
    const float* fx = g_f + 1 * RANK * NPTS;
    const float* fy = g_f + 2 * RANK * NPTS;
    const float* fz = g_f + 3 * RANK * NPTS;
    g_A[idx] = ft[r * NPTS + i] * fx[r * NPTS + j];
    g_B[idx] = fy[r * NPTS + i] * fz[r * NPTS + j];
}

// ---------------------------------------------------------------------------
// Kernel 3: C[9216,9216] = A^T(9216x32) * B(32x9216) — single-shot K=32 SGEMM.
// Block tile 128x256, 256 threads, per-thread 8x16 via fma.rn.f32x2.
// ---------------------------------------------------------------------------
__device__ __forceinline__ unsigned long long ffma2(unsigned long long a,
                                                    unsigned long long b,
                                                    unsigned long long c) {
    unsigned long long d;
    asm("fma.rn.f32x2 %0, %1, %2, %3;" : "=l"(d) : "l"(a), "l"(b), "l"(c));
    return d;
}
__device__ __forceinline__ unsigned long long pack2(float lo, float hi) {
    unsigned long long d;
    asm("mov.b64 %0, {%1, %2};" : "=l"(d) : "f"(lo), "f"(hi));
    return d;
}

__global__ void __launch_bounds__(256, 1) cp_gemm(float* __restrict__ out) {
    __shared__ float sA[RANK * BM];   // 16 KB, [r][m]
    __shared__ float sB[RANK * BN];   // 32 KB, [r][n]

    const int tid = threadIdx.x;
    const int m0 = blockIdx.x * BM;
    const int n0 = blockIdx.y * BN;

    // Fill sA: 1024 float4 (32 rows x 32 float4)
#pragma unroll
    for (int k = 0; k < 4; k++) {
        int idx = tid + k * 256;
        int r = idx >> 5, mo = idx & 31;
        ((float4*)sA)[idx] = *(const float4*)(g_A + r * MTOT + m0 + mo * 4);
    }
    // Fill sB: 2048 float4 (32 rows x 64 float4)
#pragma unroll
    for (int k = 0; k < 8; k++) {
        int idx = tid + k * 256;
        int r = idx >> 6, no = idx & 63;
        ((float4*)sB)[idx] = *(const float4*)(g_B + r * MTOT + n0 + no * 4);
    }
    __syncthreads();

    const int mg = tid >> 4;           // 0..15  -> rows  m0 + mg*8 .. +7
    const int ng = tid & 15;           // 0..15  -> cols  ng*4 + c*64, c=0..3

    unsigned long long acc[8][8];
#pragma unroll
    for (int a = 0; a < 8; a++)
#pragma unroll
        for (int b = 0; b < 8; b++) acc[a][b] = 0ULL;

    const float* pa = sA + mg * 8;
    const float* pb = sB + ng * 4;

#pragma unroll 4
    for (int r = 0; r < RANK; r++) {
        const float4 a01 = *(const float4*)(pa + r * BM);
        const float4 a23 = *(const float4*)(pa + r * BM + 4);
        unsigned long long ad[8];
        ad[0] = pack2(a01.x, a01.x); ad[1] = pack2(a01.y, a01.y);
        ad[2] = pack2(a01.z, a01.z); ad[3] = pack2(a01.w, a01.w);
        ad[4] = pack2(a23.x, a23.x); ad[5] = pack2(a23.y, a23.y);
        ad[6] = pack2(a23.z, a23.z); ad[7] = pack2(a23.w, a23.w);

        unsigned long long bp[8];
#pragma unroll
        for (int c = 0; c < 4; c++) {
            const float4 bv = *(const float4*)(pb + r * BN + c * 64);
            bp[c * 2 + 0] = pack2(bv.x, bv.y);
            bp[c * 2 + 1] = pack2(bv.z, bv.w);
        }
#pragma unroll
        for (int m = 0; m < 8; m++)
#pragma unroll
            for (int p = 0; p < 8; p++)
                acc[m][p] = ffma2(ad[m], bp[p], acc[m][p]);
    }

    // Store: 8 rows x 4 chunks of 4 floats (16B stores, fully coalesced per warp)
#pragma unroll
    for (int m = 0; m < 8; m++) {
        float* crow = out + (size_t)(m0 + mg * 8 + m) * MTOT + n0 + ng * 4;
#pragma unroll
        for (int c = 0; c < 4; c++) {
            ulonglong2 v;
            v.x = acc[m][c * 2 + 0];
            v.y = acc[m][c * 2 + 1];
            *(ulonglong2*)(crow + c * 64) = v;
        }
    }
}

// ---------------------------------------------------------------------------
extern "C" void kernel_launch(void* const* d_in, const int* in_sizes, int n_in,
                              void* d_out, int out_size) {
    const float* t  = (const float*)d_in[0];
    const float* x  = (const float*)d_in[1];
    const float* y  = (const float*)d_in[2];
    const float* z  = (const float*)d_in[3];
    const float* W1 = (const float*)d_in[4];
    const float* b1 = (const float*)d_in[5];
    const float* W2 = (const float*)d_in[6];
    const float* b2 = (const float*)d_in[7];
    const float* W3 = (const float*)d_in[8];
    const float* b3 = (const float*)d_in[9];
    float* out = (float*)d_out;

    mlp_kernel<<<4, 384>>>(t, x, y, z, W1, b1, W2, b2, W3, b3);
    prep_kernel<<<(RANK * MTOT) / 256, 256>>>();
    cp_gemm<<<dim3(MTOT / BM, MTOT / BN), 256>>>(out);
}

// round 4
// speedup vs baseline: 2.3942x; 1.2669x over previous
#include <cuda_runtime.h>
#include <cuda_bf16.h>
#include <cstdint>
#include <cstring>

#define NPTS 96
#define HDIM 64
#define RANK 32
#define MTOT 9216
#define BM 128
#define BN 128
#define KTOT 96              // split-bf16: [Ah,Ah,Al] x [Bh,Bl,Bh]
#define KPAD 104             // row pitch in bf16 elems (208 B) -> conflict-free ldmatrix
#define MTILES 72
#define NTILES 72

__device__ float g_f[4 * RANK * NPTS];
// Per-tile row-major operand images, row pitch KPAD bf16 (pad zeroed).
__device__ __nv_bfloat16 g_Abf[MTILES * BM * KPAD];
__device__ __nv_bfloat16 g_Bbf[NTILES * BN * KPAD];

// ---------------------------------------------------------------------------
__device__ __forceinline__ uint32_t smem_u32(const void* p) {
    uint32_t a;
    asm("{ .reg .u64 t; cvta.to.shared.u64 t, %1; cvt.u32.u64 %0, t; }" : "=r"(a) : "l"(p));
    return a;
}
__device__ __forceinline__ void ldm_x4(uint32_t& r0, uint32_t& r1, uint32_t& r2,
                                       uint32_t& r3, uint32_t addr) {
    asm volatile("ldmatrix.sync.aligned.m8n8.x4.shared.b16 {%0,%1,%2,%3}, [%4];"
                 : "=r"(r0), "=r"(r1), "=r"(r2), "=r"(r3) : "r"(addr));
}
__device__ __forceinline__ void mma_bf16(float* c, uint32_t a0, uint32_t a1,
                                         uint32_t a2, uint32_t a3,
                                         uint32_t b0, uint32_t b1) {
    asm volatile(
        "mma.sync.aligned.m16n8k16.row.col.f32.bf16.bf16.f32 "
        "{%0,%1,%2,%3}, {%4,%5,%6,%7}, {%8,%9}, {%0,%1,%2,%3};"
        : "+f"(c[0]), "+f"(c[1]), "+f"(c[2]), "+f"(c[3])
        : "r"(a0), "r"(a1), "r"(a2), "r"(a3), "r"(b0), "r"(b1));
}

// ---------------------------------------------------------------------------
// Kernel 1: four tiny MLPs, warp-per-point. grid = 4 axes x 6 groups, 512 thr.
// ---------------------------------------------------------------------------
__global__ void __launch_bounds__(512) mlp_kernel(
    const float* __restrict__ t, const float* __restrict__ x,
    const float* __restrict__ y, const float* __restrict__ z,
    const float* __restrict__ W1, const float* __restrict__ b1,
    const float* __restrict__ W2, const float* __restrict__ b2,
    const float* __restrict__ W3, const float* __restrict__ b3) {
    const int axis = blockIdx.x / 6;
    const int grp  = blockIdx.x % 6;
    const int tid = threadIdx.x;
    const int wid = tid >> 5, lane = tid & 31;
    const int n = grp * 16 + wid;

    __shared__ float sW2[HDIM * HDIM];
    __shared__ float sW3[HDIM * RANK];
    for (int i = tid; i < HDIM * HDIM; i += 512) sW2[i] = W2[axis * HDIM * HDIM + i];
    for (int i = tid; i < HDIM * RANK; i += 512) sW3[i] = W3[axis * HDIM * RANK + i];
    __syncthreads();

    const float* coord = (axis == 0) ? t : (axis == 1) ? x : (axis == 2) ? y : z;
    const float c = coord[n];

    float t1a = tanhf(fmaf(c, __ldg(&W1[axis * HDIM + lane]),      __ldg(&b1[axis * HDIM + lane])));
    float t1b = tanhf(fmaf(c, __ldg(&W1[axis * HDIM + 32 + lane]), __ldg(&b1[axis * HDIM + 32 + lane])));

    float a0 = 0.f, a1 = 0.f;
#pragma unroll
    for (int j = 0; j < 32; j++) {
        float hj = __shfl_sync(0xffffffffu, t1a, j);
        a0 = fmaf(hj, sW2[j * HDIM + lane], a0);
        a1 = fmaf(hj, sW2[j * HDIM + 32 + lane], a1);
    }
#pragma unroll
    for (int j = 0; j < 32; j++) {
        float hj = __shfl_sync(0xffffffffu, t1b, j);
        a0 = fmaf(hj, sW2[(j + 32) * HDIM + lane], a0);
        a1 = fmaf(hj, sW2[(j + 32) * HDIM + 32 + lane], a1);
    }
    float h2a = tanhf(a0 + __ldg(&b2[axis * HDIM + lane]));
    float h2b = tanhf(a1 + __ldg(&b2[axis * HDIM + 32 + lane]));

    float r0 = 0.f;
#pragma unroll
    for (int k = 0; k < 32; k++) {
        float hk = __shfl_sync(0xffffffffu, h2a, k);
        r0 = fmaf(hk, sW3[k * RANK + lane], r0);
    }
#pragma unroll
    for (int k = 0; k < 32; k++) {
        float hk = __shfl_sync(0xffffffffu, h2b, k);
        r0 = fmaf(hk, sW3[(k + 32) * RANK + lane], r0);
    }
    g_f[axis * RANK * NPTS + lane * NPTS + n] = r0 + __ldg(&b3[axis * RANK + lane]);
}

// ---------------------------------------------------------------------------
// Kernel 2: build split-bf16 operand rows. One thread per output row.
// A row m: k=r -> Ah, k=32+r -> Ah, k=64+r -> Al.
// B row n: k=r -> Bh, k=32+r -> Bl, k=64+r -> Bh.
// ---------------------------------------------------------------------------
__global__ void __launch_bounds__(256) prep_kernel() {
    const int idx = blockIdx.x * 256 + threadIdx.x;   // 0 .. 2*MTOT
    const int isB = (idx >= MTOT);
    const int m = isB ? idx - MTOT : idx;
    const int i = m / NPTS, j = m - i * NPTS;

    const float* f0 = g_f + (isB ? 2 : 0) * RANK * NPTS;
    const float* f1 = g_f + (isB ? 3 : 1) * RANK * NPTS;

    __align__(16) __nv_bfloat16 buf[KPAD];
#pragma unroll
    for (int k = KTOT; k < KPAD; k++) buf[k] = __float2bfloat16_rn(0.f);

#pragma unroll
    for (int r = 0; r < RANK; r++) {
        const float v = f0[r * NPTS + i] * f1[r * NPTS + j];
        const __nv_bfloat16 hi = __float2bfloat16_rn(v);
        const __nv_bfloat16 lo = __float2bfloat16_rn(v - __bfloat162float(hi));
        buf[r] = hi;
        buf[32 + r] = isB ? lo : hi;
        buf[64 + r] = isB ? hi : lo;
    }

    __nv_bfloat16* dst = (isB ? g_Bbf : g_Abf) + (size_t)(m >> 7) * BM * KPAD
                         + (size_t)(m & 127) * KPAD;
    const float4* s = (const float4*)buf;
    float4* d = (float4*)dst;
#pragma unroll
    for (int q = 0; q < KPAD / 8; q++) d[q] = s[q];
}

// ---------------------------------------------------------------------------
// Kernel 3: 128x128 GEMM tile via mma.sync bf16, K=96 resident in smem.
// 8 warps in a 2(m) x 4(n) grid; warp tile 64x32.
// ---------------------------------------------------------------------------
#define TILE_BYTES (BM * KPAD * 2)    // 26624
#define SM_TOTAL   (2 * TILE_BYTES)   // 53248

__global__ void __launch_bounds__(256, 2) cp_gemm(float* __restrict__ out) {
    extern __shared__ char smem[];
    char* sA = smem;
    char* sB = smem + TILE_BYTES;

    const int tid = threadIdx.x;
    const int wid = tid >> 5, lane = tid & 31;
    const int wm = wid >> 2;          // 0..1 -> m offset 64*wm
    const int wn = wid & 3;           // 0..3 -> n offset 32*wn

    // Load tiles (pure float4 memcpy, images pre-packed).
    {
        const float4* srcA = (const float4*)(g_Abf + (size_t)blockIdx.x * BM * KPAD);
        const float4* srcB = (const float4*)(g_Bbf + (size_t)blockIdx.y * BN * KPAD);
        float4* dA = (float4*)sA;
        float4* dB = (float4*)sB;
        for (int k = tid; k < TILE_BYTES / 16; k += 256) {
            dA[k] = srcA[k];
            dB[k] = srcB[k];
        }
    }
    __syncthreads();

    const uint32_t sAu = smem_u32(sA);
    const uint32_t sBu = smem_u32(sB);
    const int lrow = lane & 15;
    const int lcolb = (lane >> 4) << 4;   // byte offset of k-half (8 bf16 = 16 B)

    float acc[4][4][4];
#pragma unroll
    for (int a = 0; a < 4; a++)
#pragma unroll
        for (int b = 0; b < 4; b++)
#pragma unroll
            for (int q = 0; q < 4; q++) acc[a][b][q] = 0.f;

#pragma unroll
    for (int s = 0; s < 6; s++) {
        const int kb = s * 32;   // byte offset of this k16 step (16 bf16 = 32 B)

        uint32_t A[4][4];
#pragma unroll
        for (int mf = 0; mf < 4; mf++) {
            const uint32_t addr = sAu + (uint32_t)(wm * 64 + mf * 16 + lrow) * (KPAD * 2)
                                  + kb + lcolb;
            ldm_x4(A[mf][0], A[mf][1], A[mf][2], A[mf][3], addr);
        }
        uint32_t B[2][4];
#pragma unroll
        for (int nh = 0; nh < 2; nh++) {
            const uint32_t addr = sBu + (uint32_t)(wn * 32 + nh * 16 + lrow) * (KPAD * 2)
                                  + kb + lcolb;
            ldm_x4(B[nh][0], B[nh][1], B[nh][2], B[nh][3], addr);
        }
#pragma unroll
        for (int mf = 0; mf < 4; mf++)
#pragma unroll
            for (int nf = 0; nf < 4; nf++) {
                const int nh = nf >> 1, nl = nf & 1;
                mma_bf16(acc[mf][nf], A[mf][0], A[mf][1], A[mf][2], A[mf][3],
                         B[nh][nl], B[nh][nl + 2]);
            }
    }

    // Epilogue: direct coalesced STG.64.
    const int m0 = blockIdx.x * BM + wm * 64;
    const int n0 = blockIdx.y * BN + wn * 32;
    const int rg = lane >> 2;          // 0..7
    const int cg = (lane & 3) * 2;     // 0,2,4,6
#pragma unroll
    for (int mf = 0; mf < 4; mf++)
#pragma unroll
        for (int nf = 0; nf < 4; nf++) {
            float* p0 = out + (size_t)(m0 + mf * 16 + rg) * MTOT + n0 + nf * 8 + cg;
            float* p1 = p0 + (size_t)8 * MTOT;
            *(float2*)p0 = make_float2(acc[mf][nf][0], acc[mf][nf][1]);
            *(float2*)p1 = make_float2(acc[mf][nf][2], acc[mf][nf][3]);
        }
}

// ---------------------------------------------------------------------------
extern "C" void kernel_launch(void* const* d_in, const int* in_sizes, int n_in,
                              void* d_out, int out_size) {
    const float* t  = (const float*)d_in[0];
    const float* x  = (const float*)d_in[1];
    const float* y  = (const float*)d_in[2];
    const float* z  = (const float*)d_in[3];
    const float* W1 = (const float*)d_in[4];
    const float* b1 = (const float*)d_in[5];
    const float* W2 = (const float*)d_in[6];
    const float* b2 = (const float*)d_in[7];
    const float* W3 = (const float*)d_in[8];
    const float* b3 = (const float*)d_in[9];
    float* out = (float*)d_out;

    cudaFuncSetAttribute(cp_gemm, cudaFuncAttributeMaxDynamicSharedMemorySize, SM_TOTAL);

    mlp_kernel<<<24, 512>>>(t, x, y, z, W1, b1, W2, b2, W3, b3);
    prep_kernel<<<(2 * MTOT) / 256, 256>>>();
    cp_gemm<<<dim3(MTILES, NTILES), 256, SM_TOTAL>>>(out);
}

// round 5
// speedup vs baseline: 3.0430x; 1.2710x over previous
#include <cuda_runtime.h>
#include <cuda_bf16.h>
#include <cstdint>

#define NPTS 96
#define HDIM 64
#define RANK 32
#define MTOT 9216
#define BM 128
#define BN 128
#define KTOT 96              // split-bf16: [Ah,Ah,Al] x [Bh,Bl,Bh]
#define KPAD 104             // 208-B row pitch -> conflict-free ldmatrix
#define MTILES 72
#define NTILES 72
#define TILE_BYTES (BM * KPAD * 2)   // 26624
#define TILE16 (TILE_BYTES / 16)     // 1664
#define SM_TOTAL (3 * TILE_BYTES)    // A + B0 + B1 = 79872

__device__ float g_f[4 * RANK * NPTS];
__device__ __nv_bfloat16 g_Abf[MTILES * BM * KPAD];
__device__ __nv_bfloat16 g_Bbf[NTILES * BN * KPAD];

// ---------------------------------------------------------------------------
__device__ __forceinline__ uint32_t smem_u32(const void* p) {
    uint32_t a;
    asm("{ .reg .u64 t; cvta.to.shared.u64 t, %1; cvt.u32.u64 %0, t; }" : "=r"(a) : "l"(p));
    return a;
}
__device__ __forceinline__ void cp16(uint32_t s, const void* g) {
    asm volatile("cp.async.cg.shared.global [%0], [%1], 16;" :: "r"(s), "l"(g));
}
#define CP_COMMIT() asm volatile("cp.async.commit_group;" ::: "memory")
#define CP_WAIT(n)  asm volatile("cp.async.wait_group %0;" :: "n"(n) : "memory")

__device__ __forceinline__ void ldm_x4(uint32_t& r0, uint32_t& r1, uint32_t& r2,
                                       uint32_t& r3, uint32_t addr) {
    asm volatile("ldmatrix.sync.aligned.m8n8.x4.shared.b16 {%0,%1,%2,%3}, [%4];"
                 : "=r"(r0), "=r"(r1), "=r"(r2), "=r"(r3) : "r"(addr));
}
__device__ __forceinline__ void mma_bf16(float* c, uint32_t a0, uint32_t a1,
                                         uint32_t a2, uint32_t a3,
                                         uint32_t b0, uint32_t b1) {
    asm volatile(
        "mma.sync.aligned.m16n8k16.row.col.f32.bf16.bf16.f32 "
        "{%0,%1,%2,%3}, {%4,%5,%6,%7}, {%8,%9}, {%0,%1,%2,%3};"
        : "+f"(c[0]), "+f"(c[1]), "+f"(c[2]), "+f"(c[3])
        : "r"(a0), "r"(a1), "r"(a2), "r"(a3), "r"(b0), "r"(b1));
}
__device__ __forceinline__ float ftanh(float v) {
    v = fminf(fmaxf(v, -15.f), 15.f);
    const float e = __expf(2.f * v);
    return __fdividef(e - 1.f, e + 1.f);
}

// ---------------------------------------------------------------------------
// Kernel 1: four tiny MLPs, warp-per-point. grid = 4 axes x 24, 128 threads.
// ---------------------------------------------------------------------------
__global__ void __launch_bounds__(128) mlp_kernel(
    const float* __restrict__ t, const float* __restrict__ x,
    const float* __restrict__ y, const float* __restrict__ z,
    const float* __restrict__ W1, const float* __restrict__ b1,
    const float* __restrict__ W2, const float* __restrict__ b2,
    const float* __restrict__ W3, const float* __restrict__ b3) {
    const int axis = blockIdx.x / 24;
    const int grp  = blockIdx.x % 24;
    const int tid = threadIdx.x;
    const int wid = tid >> 5, lane = tid & 31;
    const int n = grp * 4 + wid;

    __shared__ float sW2[HDIM * HDIM];
    __shared__ float sW3[HDIM * RANK];
    for (int i = tid; i < HDIM * HDIM; i += 128) sW2[i] = W2[axis * HDIM * HDIM + i];
    for (int i = tid; i < HDIM * RANK; i += 128) sW3[i] = W3[axis * HDIM * RANK + i];
    __syncthreads();

    const float* coord = (axis == 0) ? t : (axis == 1) ? x : (axis == 2) ? y : z;
    const float c = coord[n];

    float t1a = ftanh(fmaf(c, __ldg(&W1[axis * HDIM + lane]),      __ldg(&b1[axis * HDIM + lane])));
    float t1b = ftanh(fmaf(c, __ldg(&W1[axis * HDIM + 32 + lane]), __ldg(&b1[axis * HDIM + 32 + lane])));

    float a0 = 0.f, a1 = 0.f;
#pragma unroll
    for (int j = 0; j < 32; j++) {
        float hj = __shfl_sync(0xffffffffu, t1a, j);
        a0 = fmaf(hj, sW2[j * HDIM + lane], a0);
        a1 = fmaf(hj, sW2[j * HDIM + 32 + lane], a1);
    }
#pragma unroll
    for (int j = 0; j < 32; j++) {
        float hj = __shfl_sync(0xffffffffu, t1b, j);
        a0 = fmaf(hj, sW2[(j + 32) * HDIM + lane], a0);
        a1 = fmaf(hj, sW2[(j + 32) * HDIM + 32 + lane], a1);
    }
    float h2a = ftanh(a0 + __ldg(&b2[axis * HDIM + lane]));
    float h2b = ftanh(a1 + __ldg(&b2[axis * HDIM + 32 + lane]));

    float r0 = 0.f;
#pragma unroll
    for (int k = 0; k < 32; k++) {
        float hk = __shfl_sync(0xffffffffu, h2a, k);
        r0 = fmaf(hk, sW3[k * RANK + lane], r0);
    }
#pragma unroll
    for (int k = 0; k < 32; k++) {
        float hk = __shfl_sync(0xffffffffu, h2b, k);
        r0 = fmaf(hk, sW3[(k + 32) * RANK + lane], r0);
    }
    g_f[axis * RANK * NPTS + lane * NPTS + n] = r0 + __ldg(&b3[axis * RANK + lane]);
}

// ---------------------------------------------------------------------------
// Kernel 2: build split-bf16 operand rows. One thread per output row.
// ---------------------------------------------------------------------------
__global__ void __launch_bounds__(256) prep_kernel() {
    const int idx = blockIdx.x * 256 + threadIdx.x;
    const int isB = (idx >= MTOT);
    const int m = isB ? idx - MTOT : idx;
    const int i = m / NPTS, j = m - i * NPTS;

    const float* f0 = g_f + (isB ? 2 : 0) * RANK * NPTS;
    const float* f1 = g_f + (isB ? 3 : 1) * RANK * NPTS;

    __align__(16) __nv_bfloat16 buf[KPAD];
#pragma unroll
    for (int k = KTOT; k < KPAD; k++) buf[k] = __float2bfloat16_rn(0.f);

#pragma unroll
    for (int r = 0; r < RANK; r++) {
        const float v = f0[r * NPTS + i] * f1[r * NPTS + j];
        const __nv_bfloat16 hi = __float2bfloat16_rn(v);
        const __nv_bfloat16 lo = __float2bfloat16_rn(v - __bfloat162float(hi));
        buf[r] = hi;
        buf[32 + r] = isB ? lo : hi;
        buf[64 + r] = isB ? hi : lo;
    }

    __nv_bfloat16* dst = (isB ? g_Bbf : g_Abf) + (size_t)(m >> 7) * BM * KPAD
                         + (size_t)(m & 127) * KPAD;
    const float4* s = (const float4*)buf;
    float4* d = (float4*)dst;
#pragma unroll
    for (int q = 0; q < KPAD / 8; q++) d[q] = s[q];
}

// ---------------------------------------------------------------------------
// Kernel 3: 1 A-tile x 2 B-tiles per CTA, cp.async prefetch, mma.sync bf16.
// ---------------------------------------------------------------------------
__device__ __forceinline__ void compute_tile(uint32_t sAu, uint32_t sBu,
                                             float* __restrict__ out,
                                             int m0, int n0, int wm, int wn, int lane) {
    const int lrow = lane & 15;
    const int lcolb = (lane >> 4) << 4;

    float acc[4][4][4];
#pragma unroll
    for (int a = 0; a < 4; a++)
#pragma unroll
        for (int b = 0; b < 4; b++)
#pragma unroll
            for (int q = 0; q < 4; q++) acc[a][b][q] = 0.f;

#pragma unroll
    for (int s = 0; s < 6; s++) {
        const int kb = s * 32;
        uint32_t A[4][4];
#pragma unroll
        for (int mf = 0; mf < 4; mf++) {
            const uint32_t addr = sAu + (uint32_t)(wm * 64 + mf * 16 + lrow) * (KPAD * 2)
                                  + kb + lcolb;
            ldm_x4(A[mf][0], A[mf][1], A[mf][2], A[mf][3], addr);
        }
        uint32_t B[2][4];
#pragma unroll
        for (int nh = 0; nh < 2; nh++) {
            const uint32_t addr = sBu + (uint32_t)(wn * 32 + nh * 16 + lrow) * (KPAD * 2)
                                  + kb + lcolb;
            ldm_x4(B[nh][0], B[nh][1], B[nh][2], B[nh][3], addr);
        }
#pragma unroll
        for (int mf = 0; mf < 4; mf++)
#pragma unroll
            for (int nf = 0; nf < 4; nf++) {
                const int nh = nf >> 1, nl = nf & 1;
                mma_bf16(acc[mf][nf], A[mf][0], A[mf][1], A[mf][2], A[mf][3],
                         B[nh][nl], B[nh][nl + 2]);
            }
    }

    const int rg = lane >> 2;
    const int cg = (lane & 3) * 2;
#pragma unroll
    for (int mf = 0; mf < 4; mf++)
#pragma unroll
        for (int nf = 0; nf < 4; nf++) {
            float* p0 = out + (size_t)(m0 + wm * 64 + mf * 16 + rg) * MTOT
                        + n0 + wn * 32 + nf * 8 + cg;
            float* p1 = p0 + (size_t)8 * MTOT;
            *(float2*)p0 = make_float2(acc[mf][nf][0], acc[mf][nf][1]);
            *(float2*)p1 = make_float2(acc[mf][nf][2], acc[mf][nf][3]);
        }
}

__global__ void __launch_bounds__(256, 2) cp_gemm(float* __restrict__ out) {
    extern __shared__ char smem[];
    const uint32_t sAu  = smem_u32(smem);
    const uint32_t sB0u = sAu + TILE_BYTES;
    const uint32_t sB1u = sAu + 2 * TILE_BYTES;

    const int tid = threadIdx.x;
    const int wid = tid >> 5, lane = tid & 31;
    const int wm = wid >> 2;
    const int wn = wid & 3;
    const int m0 = blockIdx.x * BM;
    const int nt0 = blockIdx.y * 2;

    const char* gA  = (const char*)(g_Abf + (size_t)blockIdx.x * BM * KPAD);
    const char* gB0 = (const char*)(g_Bbf + (size_t)(nt0 + 0) * BN * KPAD);
    const char* gB1 = (const char*)(g_Bbf + (size_t)(nt0 + 1) * BN * KPAD);

    for (int idx = tid; idx < TILE16; idx += 256) cp16(sAu + idx * 16, gA + idx * 16);
    CP_COMMIT();
    for (int idx = tid; idx < TILE16; idx += 256) cp16(sB0u + idx * 16, gB0 + idx * 16);
    CP_COMMIT();
    for (int idx = tid; idx < TILE16; idx += 256) cp16(sB1u + idx * 16, gB1 + idx * 16);
    CP_COMMIT();

    CP_WAIT(1);              // A + B0 complete; B1 still in flight
    __syncthreads();
    compute_tile(sAu, sB0u, out, m0, (nt0 + 0) * BN, wm, wn, lane);

    CP_WAIT(0);              // B1 complete
    __syncthreads();
    compute_tile(sAu, sB1u, out, m0, (nt0 + 1) * BN, wm, wn, lane);
}

// ---------------------------------------------------------------------------
extern "C" void kernel_launch(void* const* d_in, const int* in_sizes, int n_in,
                              void* d_out, int out_size) {
    const float* t  = (const float*)d_in[0];
    const float* x  = (const float*)d_in[1];
    const float* y  = (const float*)d_in[2];
    const float* z  = (const float*)d_in[3];
    const float* W1 = (const float*)d_in[4];
    const float* b1 = (const float*)d_in[5];
    const float* W2 = (const float*)d_in[6];
    const float* b2 = (const float*)d_in[7];
    const float* W3 = (const float*)d_in[8];
    const float* b3 = (const float*)d_in[9];
    float* out = (float*)d_out;

    cudaFuncSetAttribute(cp_gemm, cudaFuncAttributeMaxDynamicSharedMemorySize, SM_TOTAL);

    mlp_kernel<<<96, 128>>>(t, x, y, z, W1, b1, W2, b2, W3, b3);
    prep_kernel<<<(2 * MTOT) / 256, 256>>>();
    cp_gemm<<<dim3(MTILES, NTILES / 2), 256, SM_TOTAL>>>(out);
}